// round 8
// baseline (speedup 1.0000x reference)
#include <cuda_runtime.h>

#define BATCH 65536
#define THR_A 128
#define NBLK_A (BATCH / THR_A)

#define THR_B 384
#define ELEM_B 256
#define NBLK_B (BATCH / ELEM_B)    // 256 blocks
#define CH 64                      // elements per chunk
#define NCHUNK (ELEM_B / CH)

typedef unsigned long long ull;

// fc1 output, pre-paired: g_x2[j2*BATCH + i] = (x[2*j2], x[2*j2+1])
__device__ float2 g_x2[32 * BATCH];

__device__ __forceinline__ float lrelu(float v) { return v > 0.f ? v : 0.01f * v; }

__device__ __forceinline__ ull pack2(float lo, float hi) {
    ull r; asm("mov.b64 %0, {%1,%2};" : "=l"(r) : "f"(lo), "f"(hi)); return r;
}
__device__ __forceinline__ void unpack2(ull v, float& lo, float& hi) {
    asm("mov.b64 {%0,%1}, %2;" : "=f"(lo), "=f"(hi) : "l"(v));
}
__device__ __forceinline__ void ffma2(ull& d, ull a, ull b) {
    asm("fma.rn.f32x2 %0, %1, %2, %0;" : "+l"(d) : "l"(a), "l"(b));
}
__device__ __forceinline__ void addx2(ull& d, ull a) {
    asm("add.rn.f32x2 %0, %0, %1;" : "+l"(d) : "l"(a));
}
__device__ __forceinline__ float sum2(ull v) {
    float lo, hi; unpack2(v, lo, hi); return lo + hi;
}
__device__ __forceinline__ float sigm(float x) { return 1.f / (1.f + __expf(-x)); }

// ---------------------------------------------------------------------------
// Kernel A smem partition (floats) — R3 layout
// ---------------------------------------------------------------------------
#define SOBS   0        // 128*85 = 10880   (prologue: aliases W staging 4096)
#define SWFC1  10880    // 5760
#define SWINT  16640    // 1536  transposed [sel][j][f]
#define SWO1   18176    // 320
#define SWO2   18496    // 512
#define SBIN   19008    // 192
#define SWA    19200    // 128 interleaved (Wa1[j],Wa2[j])
#define SBO1   19328    // 32
#define SBO2   19360    // 16
#define SWO3   19376    // 16
#define SBFC1  19392    // 64
#define SBO3   19456    // 1
#define SM_A_FLOATS 19460

__global__ __launch_bounds__(THR_A) void k_att(
    const float* __restrict__ obs,
    const float* __restrict__ w_in0, const float* __restrict__ b_in0,
    const float* __restrict__ w_in1, const float* __restrict__ b_in1,
    const float* __restrict__ w_in2, const float* __restrict__ b_in2,
    const float* __restrict__ W,     const float* __restrict__ a,
    const float* __restrict__ w_o1,  const float* __restrict__ b_o1,
    const float* __restrict__ w_o2,  const float* __restrict__ b_o2,
    const float* __restrict__ w_o3,  const float* __restrict__ b_o3,
    const float* __restrict__ w_fc1, const float* __restrict__ b_fc1)
{
    extern __shared__ float sm[];
    const int tid = threadIdx.x;

    // ---- Prologue 0: Wa = W @ a (W staged into the obs region, then freed) ----
    {
        float4* dW = (float4*)(sm + SOBS);
        const float4* sW = (const float4*)W;
        for (int idx = tid; idx < 1024; idx += THR_A) dW[idx] = sW[idx];
        __syncthreads();
        if (tid < 64) {
            const float* wr = sm + SOBS + tid * 64;
            float s1 = 0.f, s2 = 0.f;
            #pragma unroll 16
            for (int j = 0; j < 64; j++) {
                float w = wr[j];
                s1 = fmaf(w, a[j], s1);
                s2 = fmaf(w, a[64 + j], s2);
            }
            sm[SWA + 2 * tid]     = s1;
            sm[SWA + 2 * tid + 1] = s2;
        }
        __syncthreads();
    }

    // ---- Prologue 1: weights + obs staging ----
    for (int idx = tid; idx < 1536; idx += THR_A) {
        int sel = idx >> 9, rem = idx & 511;
        int j = rem >> 3, f = rem & 7;
        const float* w = (sel == 0) ? w_in0 : ((sel == 1) ? w_in1 : w_in2);
        sm[SWINT + idx] = w[f * 64 + j];
    }
    for (int idx = tid; idx < 192; idx += THR_A)
        sm[SBIN + idx] = (idx < 64) ? b_in0[idx] : ((idx < 128) ? b_in1[idx - 64] : b_in2[idx - 128]);
    for (int idx = tid; idx < 320; idx += THR_A) sm[SWO1 + idx] = w_o1[idx];
    if (tid < 32) sm[SBO1 + tid] = b_o1[tid];
    for (int idx = tid; idx < 512; idx += THR_A) sm[SWO2 + idx] = w_o2[idx];
    if (tid < 16) { sm[SBO2 + tid] = b_o2[tid]; sm[SWO3 + tid] = w_o3[tid]; }
    if (tid == 0) sm[SBO3] = b_o3[0];
    for (int idx = tid; idx < 5760; idx += THR_A) sm[SWFC1 + idx] = w_fc1[idx];
    if (tid < 64) sm[SBFC1 + tid] = b_fc1[tid];
    {   // coalesced obs block copy (128 rows * 85 floats = 2720 float4)
        const float4* src = (const float4*)(obs + (size_t)blockIdx.x * THR_A * 85);
        float4* dst = (float4*)(sm + SOBS);
        for (int idx = tid; idx < 2720; idx += THR_A) dst[idx] = src[idx];
    }
    __syncthreads();

    const int i = blockIdx.x * THR_A + tid;
    const float* so = sm + SOBS + tid * 85;   // gcd(85,32)=1 -> conflict-free

    // ================= Phase 1: attention path -> obs_out =================
    float wh1[10], wh2[10];
    const ull* wa2 = (const ull*)(sm + SWA);

    for (int t = 0; t < 10; t++) {
        const int sel = (t < 5) ? 0 : ((t < 9) ? 1 : 2);
        const float* wt = sm + SWINT + sel * 512;
        const float* bb = sm + SBIN + sel * 64;
        const int base = 4 + 8 * t;

        float ov[8];
        #pragma unroll
        for (int f = 0; f < 8; f++) {
            int k = base + f; if (k >= 80) k -= 80;
            ov[f] = so[k];
        }
        ull ovp[4];
        #pragma unroll
        for (int m = 0; m < 4; m++) ovp[m] = pack2(ov[2 * m], ov[2 * m + 1]);

        ull s12 = pack2(0.f, 0.f);
        #pragma unroll 8
        for (int j = 0; j < 64; j++) {
            const ulonglong2* wj = (const ulonglong2*)(wt + j * 8);
            ulonglong2 wA = wj[0], wB = wj[1];
            ull h2 = pack2(bb[j], 0.f);
            ffma2(h2, ovp[0], wA.x);
            ffma2(h2, ovp[1], wA.y);
            ffma2(h2, ovp[2], wB.x);
            ffma2(h2, ovp[3], wB.y);
            float hv = lrelu(sum2(h2));
            ffma2(s12, pack2(hv, hv), wa2[j]);
        }
        unpack2(s12, wh1[t], wh2[t]);
    }

    // att1 softmax stats (rows u=5..9 over cols 0..4)
    float m1[5], iz1[5];
    #pragma unroll
    for (int u = 0; u < 5; u++) {
        float e0 = lrelu(wh1[5 + u] + wh2[0]);
        float e1 = lrelu(wh1[5 + u] + wh2[1]);
        float e2 = lrelu(wh1[5 + u] + wh2[2]);
        float e3 = lrelu(wh1[5 + u] + wh2[3]);
        float e4 = lrelu(wh1[5 + u] + wh2[4]);
        float m = fmaxf(fmaxf(fmaxf(e0, e1), fmaxf(e2, e3)), e4);
        float z = __expf(e0 - m) + __expf(e1 - m) + __expf(e2 - m)
                + __expf(e3 - m) + __expf(e4 - m);
        m1[u] = m; iz1[u] = 1.f / z;
    }

    float hp3[5];
    #pragma unroll
    for (int r = 0; r < 5; r++) {
        float att[10];
        float ev[5]; float m = -1e30f;
        #pragma unroll
        for (int c = 0; c < 5; c++) { ev[c] = lrelu(wh1[r] + wh2[5 + c]); m = fmaxf(m, ev[c]); }
        float z = 0.f;
        #pragma unroll
        for (int c = 0; c < 5; c++) { ev[c] = __expf(ev[c] - m); z += ev[c]; }
        float izr = 1.f / z;
        #pragma unroll
        for (int c = 0; c < 5; c++) att[c] = ev[c] * izr;
        #pragma unroll
        for (int u = 0; u < 5; u++)
            att[5 + u] = __expf(lrelu(wh1[5 + u] + wh2[r]) - m1[u]) * iz1[u];

        ull hp1[16];
        {
            const ull* b1 = (const ull*)(sm + SBO1);
            #pragma unroll
            for (int jj = 0; jj < 16; jj++) hp1[jj] = b1[jj];
        }
        #pragma unroll
        for (int c = 0; c < 10; c++) {
            ull av = pack2(att[c], att[c]);
            const ulonglong2* wr = (const ulonglong2*)(sm + SWO1 + c * 32);
            #pragma unroll
            for (int q = 0; q < 8; q++) {
                ulonglong2 w2 = wr[q];
                ffma2(hp1[2 * q], av, w2.x);
                ffma2(hp1[2 * q + 1], av, w2.y);
            }
        }
        ull hp2[8];
        {
            const ull* b2 = (const ull*)(sm + SBO2);
            #pragma unroll
            for (int j2 = 0; j2 < 8; j2++) hp2[j2] = b2[j2];
        }
        #pragma unroll
        for (int jj = 0; jj < 16; jj++) {
            float lo, hi; unpack2(hp1[jj], lo, hi);
            {
                float v = lrelu(lo); ull vv = pack2(v, v);
                const ulonglong2* wr = (const ulonglong2*)(sm + SWO2 + (2 * jj) * 16);
                #pragma unroll
                for (int q = 0; q < 4; q++) {
                    ulonglong2 w2 = wr[q];
                    ffma2(hp2[2 * q], vv, w2.x);
                    ffma2(hp2[2 * q + 1], vv, w2.y);
                }
            }
            {
                float v = lrelu(hi); ull vv = pack2(v, v);
                const ulonglong2* wr = (const ulonglong2*)(sm + SWO2 + (2 * jj + 1) * 16);
                #pragma unroll
                for (int q = 0; q < 4; q++) {
                    ulonglong2 w2 = wr[q];
                    ffma2(hp2[2 * q], vv, w2.x);
                    ffma2(hp2[2 * q + 1], vv, w2.y);
                }
            }
        }
        float s = sm[SBO3];
        #pragma unroll
        for (int j2 = 0; j2 < 8; j2++) {
            float lo, hi; unpack2(hp2[j2], lo, hi);
            s = fmaf(lrelu(lo), sm[SWO3 + 2 * j2], s);
            s = fmaf(lrelu(hi), sm[SWO3 + 2 * j2 + 1], s);
        }
        hp3[r] = lrelu(s);
    }

    // softmax(hp3) -> normalized obs_out
    float oo[5];
    {
        float m = hp3[0];
        #pragma unroll
        for (int r = 1; r < 5; r++) m = fmaxf(m, hp3[r]);
        float z = 0.f;
        #pragma unroll
        for (int r = 0; r < 5; r++) { oo[r] = __expf(hp3[r] - m); z += oo[r]; }
        float iz = 1.f / z;
        #pragma unroll
        for (int r = 0; r < 5; r++) oo[r] *= iz;
    }

    // ================= Phase 2: fc1 (packed accumulators) =================
    ull acc[32];
    {
        const ull* bf = (const ull*)(sm + SBFC1);
        #pragma unroll
        for (int jj = 0; jj < 32; jj++) acc[jj] = bf[jj];
    }
    #pragma unroll 1
    for (int k = 0; k < 85; k++) {
        float v = so[k];
        ull vv = pack2(v, v);
        const ulonglong2* wr = (const ulonglong2*)(sm + SWFC1 + k * 64);
        #pragma unroll
        for (int q = 0; q < 16; q++) {
            ulonglong2 w2 = wr[q];
            ffma2(acc[2 * q], vv, w2.x);
            ffma2(acc[2 * q + 1], vv, w2.y);
        }
    }
    #pragma unroll
    for (int u = 0; u < 5; u++) {
        ull vv = pack2(oo[u], oo[u]);
        const ulonglong2* wr = (const ulonglong2*)(sm + SWFC1 + (85 + u) * 64);
        #pragma unroll
        for (int q = 0; q < 16; q++) {
            ulonglong2 w2 = wr[q];
            ffma2(acc[2 * q], vv, w2.x);
            ffma2(acc[2 * q + 1], vv, w2.y);
        }
    }

    // relu + paired transposed store (coalesced float2 per j-pair)
    #pragma unroll
    for (int jj = 0; jj < 32; jj++) {
        float lo, hi; unpack2(acc[jj], lo, hi);
        g_x2[(size_t)jj * BATCH + i] = make_float2(fmaxf(lo, 0.f), fmaxf(hi, 0.f));
    }
}

// ---------------------------------------------------------------------------
// Kernel B: GRU + q head — weights-in-registers, broadcast activations.
// Thread t<192 holds w_ih row t (64 floats) in regs; t>=192 holds w_hh row.
// Per 64-element chunk: Phase A computes all 384 gate pre-activations per
// element via broadcast smem reads of x/h; Phase B (threads 0..63) applies
// nonlinearities + blend + q head.
// ---------------------------------------------------------------------------
#define BG     0        // G: 64 x 385 = 24640  (weight staging 192x66=12672 aliases here)
#define BX     24640    // X: 64 x 68 = 4352
#define BH     28992    // H: 64 x 68 = 4352
#define BWF    33344    // w_fc2: 64 x 6 = 384
#define BBF    33728    // b_fc2: 8
#define BQ     33736    // Q: 64 x 5 = 320
#define SM_B_FLOATS 34056

__global__ __launch_bounds__(THR_B) void k_gru(
    const float* __restrict__ hidden,
    const float* __restrict__ w_ih, const float* __restrict__ w_hh,
    const float* __restrict__ b_ih, const float* __restrict__ b_hh,
    const float* __restrict__ w_fc2, const float* __restrict__ b_fc2,
    float* __restrict__ out)
{
    extern __shared__ float sm[];
    const int tid = threadIdx.x;
    const int gside = (tid >= 192);

    // ---- load my gate row into registers (staged via smem, stride 66) ----
    ull wreg[32];
    {
        float* WST = sm + BG;
        for (int idx = tid; idx < 12288; idx += THR_B)
            WST[(idx >> 6) * 66 + (idx & 63)] = w_ih[idx];
        __syncthreads();
        if (!gside) {
            const ull* row = (const ull*)(WST + tid * 66);
            #pragma unroll
            for (int m = 0; m < 32; m++) wreg[m] = row[m];
        }
        __syncthreads();
        for (int idx = tid; idx < 12288; idx += THR_B)
            WST[(idx >> 6) * 66 + (idx & 63)] = w_hh[idx];
        __syncthreads();
        if (gside) {
            const ull* row = (const ull*)(WST + (tid - 192) * 66);
            #pragma unroll
            for (int m = 0; m < 32; m++) wreg[m] = row[m];
        }
    }
    const float bias = gside ? b_hh[tid - 192] : b_ih[tid];
    for (int idx = tid; idx < 320; idx += THR_B)
        sm[BWF + (idx / 5) * 6 + (idx % 5)] = w_fc2[idx];
    if (tid < 5) sm[BBF + tid] = b_fc2[tid];

    const int i0 = blockIdx.x * ELEM_B;
    const float* src = gside ? (sm + BH) : (sm + BX);

    for (int ch = 0; ch < NCHUNK; ch++) {
        const int e0 = i0 + ch * CH;
        __syncthreads();   // protect G/X/H reuse

        // stage X (from g_x2, coalesced over elements)
        for (int idx = tid; idx < 2048; idx += THR_B) {
            int m = idx >> 6, e = idx & 63;
            float2 v = g_x2[(size_t)m * BATCH + e0 + e];
            sm[BX + e * 68 + 2 * m]     = v.x;
            sm[BX + e * 68 + 2 * m + 1] = v.y;
        }
        // stage H (float4, coalesced)
        for (int idx = tid; idx < 1024; idx += THR_B) {
            int e = idx >> 4, k4 = idx & 15;
            float4 v = *(const float4*)(hidden + (size_t)(e0 + e) * 64 + k4 * 4);
            *(float4*)(sm + BH + e * 68 + 4 * k4) = v;
        }
        __syncthreads();

        // ---- Phase A: gate pre-activations, broadcast reads ----
        #pragma unroll 1
        for (int e = 0; e < CH; e++) {
            const ulonglong2* xr = (const ulonglong2*)(src + e * 68);
            ull acc0 = pack2(0.f, 0.f), acc1 = pack2(0.f, 0.f);
            #pragma unroll
            for (int m2 = 0; m2 < 16; m2++) {
                ulonglong2 v = xr[m2];
                ffma2(acc0, wreg[2 * m2],     v.x);
                ffma2(acc1, wreg[2 * m2 + 1], v.y);
            }
            addx2(acc0, acc1);
            sm[BG + e * 385 + tid] = sum2(acc0) + bias;
        }
        __syncthreads();

        // ---- Phase B: nonlinearities + blend + q (threads 0..63, 1 elem each) ----
        if (tid < CH) {
            const int e = tid;
            const float* Ge = sm + BG + e * 385;
            float* He = sm + BH + e * 68;
            float q0 = sm[BBF], q1 = sm[BBF + 1], q2 = sm[BBF + 2],
                  q3 = sm[BBF + 3], q4 = sm[BBF + 4];
            #pragma unroll 2
            for (int j = 0; j < 64; j++) {
                float gir = Ge[j],        giz = Ge[64 + j],  gin = Ge[128 + j];
                float ghr = Ge[192 + j],  ghz = Ge[256 + j], ghn = Ge[320 + j];
                float r  = sigm(gir + ghr);
                float zz = sigm(giz + ghz);
                float n  = 2.f * sigm(2.f * fmaf(r, ghn, gin)) - 1.f;   // tanh
                float hj = He[j];
                float hnew = fmaf(zz, hj - n, n);
                He[j] = hnew;
                const float* wf = sm + BWF + j * 6;
                q0 = fmaf(hnew, wf[0], q0);
                q1 = fmaf(hnew, wf[1], q1);
                q2 = fmaf(hnew, wf[2], q2);
                q3 = fmaf(hnew, wf[3], q3);
                q4 = fmaf(hnew, wf[4], q4);
            }
            float* Qe = sm + BQ + e * 5;
            Qe[0] = q0; Qe[1] = q1; Qe[2] = q2; Qe[3] = q3; Qe[4] = q4;
        }
        __syncthreads();

        // ---- flush (coalesced) ----
        for (int idx = tid; idx < CH * 64; idx += THR_B) {
            int e = idx >> 6, j = idx & 63;
            out[(size_t)BATCH * 5 + (size_t)(e0 + e) * 64 + j] = sm[BH + e * 68 + j];
        }
        for (int idx = tid; idx < CH * 5; idx += THR_B)
            out[(size_t)e0 * 5 + idx] = sm[BQ + idx];
    }
}

// ---------------------------------------------------------------------------
extern "C" void kernel_launch(void* const* d_in, const int* in_sizes, int n_in,
                              void* d_out, int out_size)
{
    (void)in_sizes; (void)n_in; (void)out_size;
    const float* obs    = (const float*)d_in[0];
    const float* hidden = (const float*)d_in[1];
    const float* w_in0  = (const float*)d_in[2];
    const float* b_in0  = (const float*)d_in[3];
    const float* w_in1  = (const float*)d_in[4];
    const float* b_in1  = (const float*)d_in[5];
    const float* w_in2  = (const float*)d_in[6];
    const float* b_in2  = (const float*)d_in[7];
    const float* W      = (const float*)d_in[8];
    const float* a      = (const float*)d_in[9];
    const float* w_o1   = (const float*)d_in[10];
    const float* b_o1   = (const float*)d_in[11];
    const float* w_o2   = (const float*)d_in[12];
    const float* b_o2   = (const float*)d_in[13];
    const float* w_o3   = (const float*)d_in[14];
    const float* b_o3   = (const float*)d_in[15];
    const float* w_fc1  = (const float*)d_in[16];
    const float* b_fc1  = (const float*)d_in[17];
    const float* w_ih   = (const float*)d_in[18];
    const float* w_hh   = (const float*)d_in[19];
    const float* b_ih   = (const float*)d_in[20];
    const float* b_hh   = (const float*)d_in[21];
    const float* w_fc2  = (const float*)d_in[22];
    const float* b_fc2  = (const float*)d_in[23];

    static bool attr_done = false;
    const int smemA = SM_A_FLOATS * (int)sizeof(float);   // ~77.8 KB
    const int smemB = SM_B_FLOATS * (int)sizeof(float);   // ~136.2 KB
    if (!attr_done) {
        cudaFuncSetAttribute(k_att, cudaFuncAttributeMaxDynamicSharedMemorySize, smemA);
        cudaFuncSetAttribute(k_gru, cudaFuncAttributeMaxDynamicSharedMemorySize, smemB);
        attr_done = true;
    }

    k_att<<<NBLK_A, THR_A, smemA>>>(obs,
                                    w_in0, b_in0, w_in1, b_in1, w_in2, b_in2,
                                    W, a,
                                    w_o1, b_o1, w_o2, b_o2, w_o3, b_o3,
                                    w_fc1, b_fc1);
    k_gru<<<NBLK_B, THR_B, smemB>>>(hidden, w_ih, w_hh, b_ih, b_hh,
                                    w_fc2, b_fc2, (float*)d_out);
}